// round 2
// baseline (speedup 1.0000x reference)
#include <cuda_runtime.h>
#include <cstdint>
#include <cstddef>

#define BB 16
#define SS 4096
#define DD 256
#define CL 8
#define ROWS_PER_CTA 32
#define TPR 16
#define NTHREADS 512
#define CPT 16
#define NSLOT 8          // mailbox ring depth (overwrite-safe for skew <= 6 steps)

// per-(b,t) scalars: c = eta*(1-1/n)/n ;  d = 2*alpha*c + c^2*||x||^2
__device__ float g_c[BB * SS];
__device__ float g_d[BB * SS];
__device__ float g_G0;   // ||M_init||_F^2

// ---------------------------------------------------------------------------
__global__ void coef_kernel(const float* __restrict__ x,
                            const float* __restrict__ eta_raw,
                            const float* __restrict__ alpha_raw) {
    float eta   = 0.2f / (1.0f + __expf(-eta_raw[0]));
    float alpha = 0.5f + 0.5f / (1.0f + __expf(-alpha_raw[0]));
    int warp  = (blockIdx.x * blockDim.x + threadIdx.x) >> 5;
    int lane  = threadIdx.x & 31;
    int nwarp = (gridDim.x * blockDim.x) >> 5;
    for (int row = warp; row < BB * SS; row += nwarp) {
        const float4* xr = reinterpret_cast<const float4*>(x + (size_t)row * DD);
        float4 a = xr[lane];
        float4 b = xr[lane + 32];
        float ss = a.x*a.x + a.y*a.y + a.z*a.z + a.w*a.w
                 + b.x*b.x + b.y*b.y + b.z*b.z + b.w*b.w;
        #pragma unroll
        for (int k = 16; k; k >>= 1) ss += __shfl_xor_sync(0xffffffffu, ss, k);
        if (lane == 0) {
            float n   = fmaxf(sqrtf(ss), 1e-6f);
            float inv = 1.0f / n;
            float c   = eta * (1.0f - inv) * inv;
            g_c[row]  = c;
            g_d[row]  = 2.0f * alpha * c + c * c * ss;
        }
    }
}

// ---------------------------------------------------------------------------
__global__ void g0_kernel(const float* __restrict__ M) {
    __shared__ float red[32];
    int tid = threadIdx.x;
    float s = 0.0f;
    for (int i = tid; i < DD * DD; i += 1024) {
        float v = M[i];
        s = fmaf(v, v, s);
    }
    #pragma unroll
    for (int k = 16; k; k >>= 1) s += __shfl_xor_sync(0xffffffffu, s, k);
    if ((tid & 31) == 0) red[tid >> 5] = s;
    __syncthreads();
    if (tid < 32) {
        float v = red[tid];
        #pragma unroll
        for (int k = 16; k; k >>= 1) v += __shfl_xor_sync(0xffffffffu, v, k);
        if (tid == 0) g_G0 = v;
    }
}

// ---------------------------------------------------------------------------
__device__ __forceinline__ unsigned long long pack_fu(float v, unsigned tag) {
    return (unsigned long long)__float_as_uint(v) | ((unsigned long long)tag << 32);
}
__device__ __forceinline__ unsigned long long lds_vol64(uint32_t addr) {
    unsigned long long v;
    asm volatile("ld.volatile.shared.b64 %0, [%1];" : "=l"(v) : "r"(addr));
    return v;
}
__device__ __forceinline__ void sts_vol64(uint32_t addr, unsigned long long v) {
    asm volatile("st.volatile.shared.b64 [%0], %1;" :: "r"(addr), "l"(v) : "memory");
}
__device__ __forceinline__ void st_cluster64(uint32_t raddr, unsigned long long v) {
    asm volatile("st.shared::cluster.b64 [%0], %1;" :: "r"(raddr), "l"(v) : "memory");
}

// ---------------------------------------------------------------------------
// One 8-CTA cluster per batch; M (unscaled N) lives in registers.
// No per-step barriers: lock-free seq-tagged mailboxes, 2-step-lagged
// scalar (Pc, G) recurrence replicated identically in every thread.
// ---------------------------------------------------------------------------
__global__ void __cluster_dims__(CL, 1, 1) __launch_bounds__(NTHREADS, 1)
scan_kernel(const float* __restrict__ x,
            const float* __restrict__ Minit,
            const float* __restrict__ alpha_raw,
            float* __restrict__ out) {
    __shared__ unsigned long long wslot[NSLOT][16];   // per-warp partials
    __shared__ unsigned long long cslot[NSLOT][CL];   // per-CTA partials (multicast in)

    unsigned rank;
    asm("mov.u32 %0, %%cluster_ctarank;" : "=r"(rank));
    int batch = blockIdx.x / CL;
    int tid   = threadIdx.x;
    int wid   = tid >> 5;
    int row_l = tid >> 4;
    int lir   = tid & 15;
    int row_g = (int)rank * ROWS_PER_CTA + row_l;
    int cs    = lir * CPT;

    // init mailboxes, then one-time cluster barrier (remote stores may not
    // precede our init)
    for (int i = tid; i < NSLOT * 16; i += NTHREADS)
        ((unsigned long long*)wslot)[i] = 0ull;
    for (int i = tid; i < NSLOT * CL; i += NTHREADS)
        ((unsigned long long*)cslot)[i] = 0ull;
    __syncthreads();
    asm volatile("barrier.cluster.arrive.aligned;" ::: "memory");
    asm volatile("barrier.cluster.wait.aligned;" ::: "memory");

    float alpha = 0.5f + 0.5f / (1.0f + __expf(-alpha_raw[0]));

    // precompute remote mailbox addresses (tid 0 only uses them)
    uint32_t cbase_l = (uint32_t)__cvta_generic_to_shared(&cslot[0][rank]);
    uint32_t raddr[CL];
    #pragma unroll
    for (int r = 0; r < CL; r++) {
        asm("mapa.shared::cluster.u32 %0, %1, %2;" : "=r"(raddr[r]) : "r"(cbase_l), "r"(r));
    }
    uint32_t wslot_base = (uint32_t)__cvta_generic_to_shared(&wslot[0][0]);
    uint32_t cslot_base = (uint32_t)__cvta_generic_to_shared(&cslot[0][0]);

    // load M_init fragment
    float m[CPT];
    {
        const float4* mi = reinterpret_cast<const float4*>(Minit + (size_t)row_g * DD + cs);
        #pragma unroll
        for (int j = 0; j < CPT / 4; j++) {
            float4 v = mi[j];
            m[4*j+0] = v.x; m[4*j+1] = v.y; m[4*j+2] = v.z; m[4*j+3] = v.w;
        }
    }

    const float* xb    = x   + (size_t)batch * SS * DD;
    float*       outb  = out + (size_t)batch * SS * DD;
    float*       Mf    = out + (size_t)BB * SS * DD + (size_t)batch * DD * DD;
    const float* cb    = g_c + batch * SS;
    const float* db    = g_d + batch * SS;

    // preload x_0, c_0
    float xc[CPT];
    {
        const float4* xv = reinterpret_cast<const float4*>(xb + cs);
        #pragma unroll
        for (int j = 0; j < CPT / 4; j++) {
            float4 v = xv[j];
            xc[4*j+0] = v.x; xc[4*j+1] = v.y; xc[4*j+2] = v.z; xc[4*j+3] = v.w;
        }
    }
    float c_c = cb[0];

    // replicated scalar state
    float Pc = 1.0f;       // C_{last+1} / phi  (pending scale over applied folds)
    float G  = g_G0;       // ||M_true||^2 at last consumed step + 1
    float ff1 = 1.0f;      // fold factor applied at iter t-1
    float ff2 = 1.0f;      // fold factor applied at iter t-2
    float w_prev = 0.0f;

    for (int t = 0; t < SS; t++) {
        // prefetch x_{t+1}, c_{t+1}
        float xn[CPT];
        float c_n = 0.0f;
        #pragma unroll
        for (int j = 0; j < CPT; j++) xn[j] = 0.0f;
        if (t + 1 < SS) {
            const float4* xv = reinterpret_cast<const float4*>(xb + (size_t)(t + 1) * DD + cs);
            #pragma unroll
            for (int j = 0; j < CPT / 4; j++) {
                float4 v = xv[j];
                xn[4*j+0] = v.x; xn[4*j+1] = v.y; xn[4*j+2] = v.z; xn[4*j+3] = v.w;
            }
            c_n = cb[t + 1];
        }

        // matvec: w_row = N[row] . x_t   (16-lane reduce, all lanes get w)
        float a0 = 0.0f, a1 = 0.0f;
        #pragma unroll
        for (int j = 0; j < CPT; j += 2) {
            a0 = fmaf(m[j],     xc[j],     a0);
            a1 = fmaf(m[j + 1], xc[j + 1], a1);
        }
        float w = a0 + a1;
        #pragma unroll
        for (int k = 8; k; k >>= 1) w += __shfl_xor_sync(0xffffffffu, w, k);

        // warp partial of ||w||^2 (two rows per warp)
        float z = w * w;
        z += __shfl_xor_sync(0xffffffffu, z, 16);

        // post warp partial
        int slot = t & (NSLOT - 1);
        if ((tid & 31) == 0)
            sts_vol64(wslot_base + (uint32_t)(slot * 16 + wid) * 8u, pack_fu(z, t + 1));

        // tid0: gather 16 warp partials, multicast CTA partial to all ranks
        if (tid == 0) {
            float S = 0.0f;
            #pragma unroll
            for (int k = 0; k < 16; k++) {
                uint32_t a = wslot_base + (uint32_t)(slot * 16 + k) * 8u;
                unsigned long long u;
                do { u = lds_vol64(a); } while ((unsigned)(u >> 32) != (unsigned)(t + 1));
                S += __uint_as_float((unsigned)u);
            }
            unsigned long long pv = pack_fu(S, t + 1);
            #pragma unroll
            for (int r = 0; r < CL; r++)
                st_cluster64(raddr[r] + (uint32_t)(slot * CL) * 8u, pv);
        }

        // rank-1 update (scale-free): N = alpha*N + (c*w) * x
        float g = c_c * w;
        #pragma unroll
        for (int j = 0; j < CPT; j++)
            m[j] = fmaf(g, xc[j], alpha * m[j]);

        if (t == 0) {
            if (lir == 0) outb[row_g] = w;   // Q_0 = 1
        }

        // lagged consume of step tau = t-2
        if (t >= 2) {
            int tau = t - 2;
            int cslt = tau & (NSLOT - 1);
            float wsq = 0.0f;
            #pragma unroll
            for (int r = 0; r < CL; r++) {
                uint32_t a = cslot_base + (uint32_t)(cslt * CL + r) * 8u;
                unsigned long long u;
                do { u = lds_vol64(a); } while ((unsigned)(u >> 32) != (unsigned)(tau + 1));
                wsq += __uint_as_float((unsigned)u);
            }
            // scalar recurrence for true ||M||^2 and clamp scale
            float q   = Pc * ff1 * ff2;          // C_tau / phi_at_matvec_tau
            float y2  = q * q * wsq;             // true ||y_tau||^2
            float d   = __ldg(&db[tau]);
            float Gn  = fmaf(alpha * alpha, G, d * y2);
            float fro = sqrtf(Gn);
            float s   = fminf(15.0f / (fro + 1e-6f), 1.0f);
            G  = s * s * Gn;
            Pc = Pc * s;
            // write out_{t-1} = Q_{t-1} * w_{t-1}
            float v = Pc * ff1;
            if (lir == 0) outb[(size_t)(t - 1) * DD + row_g] = v * w_prev;
            // fold pending scale into N when it gets small (uniform branch)
            float nf = 1.0f;
            if (Pc < 0.0625f) {
                nf = Pc;
                #pragma unroll
                for (int j = 0; j < CPT; j++) m[j] *= nf;
                Pc = 1.0f;
            }
            ff2 = ff1;
            ff1 = nf;
        }

        w_prev = w;
        #pragma unroll
        for (int j = 0; j < CPT; j++) xc[j] = xn[j];
        c_c = c_n;
    }

    // drain: consume tau = SS-2 (writes out[SS-1]) and tau = SS-1 (final Pc)
    #pragma unroll
    for (int dr = 0; dr < 2; dr++) {
        int tau  = SS - 2 + dr;
        int cslt = tau & (NSLOT - 1);
        float wsq = 0.0f;
        #pragma unroll
        for (int r = 0; r < CL; r++) {
            uint32_t a = cslot_base + (uint32_t)(cslt * CL + r) * 8u;
            unsigned long long u;
            do { u = lds_vol64(a); } while ((unsigned)(u >> 32) != (unsigned)(tau + 1));
            wsq += __uint_as_float((unsigned)u);
        }
        float q   = Pc * ff1 * ff2;
        float y2  = q * q * wsq;
        float d   = __ldg(&db[tau]);
        float Gn  = fmaf(alpha * alpha, G, d * y2);
        float fro = sqrtf(Gn);
        float s   = fminf(15.0f / (fro + 1e-6f), 1.0f);
        G  = s * s * Gn;
        Pc = Pc * s;
        if (dr == 0) {
            float v = Pc * ff1;
            if (lir == 0) outb[(size_t)(SS - 1) * DD + row_g] = v * w_prev;
        }
        ff2 = ff1;
        ff1 = 1.0f;
    }

    // M_final = Pc * N
    float4* mo = reinterpret_cast<float4*>(Mf + (size_t)row_g * DD + cs);
    #pragma unroll
    for (int j = 0; j < CPT / 4; j++) {
        float4 v;
        v.x = Pc * m[4*j+0]; v.y = Pc * m[4*j+1];
        v.z = Pc * m[4*j+2]; v.w = Pc * m[4*j+3];
        mo[j] = v;
    }
}

// ---------------------------------------------------------------------------
extern "C" void kernel_launch(void* const* d_in, const int* in_sizes, int n_in,
                              void* d_out, int out_size) {
    const float* x         = (const float*)d_in[0];
    const float* M_init    = (const float*)d_in[1];
    const float* eta_raw   = (const float*)d_in[2];
    const float* alpha_raw = (const float*)d_in[3];
    float*       out       = (float*)d_out;

    coef_kernel<<<256, 256>>>(x, eta_raw, alpha_raw);
    g0_kernel<<<1, 1024>>>(M_init);
    scan_kernel<<<BB * CL, NTHREADS>>>(x, M_init, alpha_raw, out);
}

// round 3
// speedup vs baseline: 4.9817x; 4.9817x over previous
#include <cuda_runtime.h>
#include <cstdint>
#include <cstddef>

#define BB 16
#define SS 4096
#define DD 256
#define CL 8
#define NROWW 16                      // row warps per CTA
#define NTHREADS (NROWW * 32 + 32)    // 544: 16 row warps + 1 reducer warp
#define RING 16
#define LAGR 8                        // row consume lag
#define LAGC 4                        // reducer consume lag

// per-(b,t) scalars: c = eta*(1-1/n)/n ;  d = 2*alpha*c + c^2*||x||^2
__device__ float g_c[BB * SS + 8];
__device__ float g_d[BB * SS + 8];
__device__ float g_G0;               // ||M_init||_F^2

// ---------------- packed f32x2 + smem helpers ------------------------------
__device__ __forceinline__ unsigned long long mul2(unsigned long long a, unsigned long long b) {
    unsigned long long d; asm("mul.rn.f32x2 %0,%1,%2;" : "=l"(d) : "l"(a), "l"(b)); return d;
}
__device__ __forceinline__ unsigned long long fma2(unsigned long long a, unsigned long long b, unsigned long long c) {
    unsigned long long d; asm("fma.rn.f32x2 %0,%1,%2,%3;" : "=l"(d) : "l"(a), "l"(b), "l"(c)); return d;
}
__device__ __forceinline__ void unpk(unsigned long long a, float& x, float& y) {
    asm("mov.b64 {%0,%1},%2;" : "=f"(x), "=f"(y) : "l"(a));
}
__device__ __forceinline__ unsigned long long pk(float lo, float hi) {
    unsigned long long d; asm("mov.b64 %0,{%1,%2};" : "=l"(d) : "f"(lo), "f"(hi)); return d;
}
__device__ __forceinline__ unsigned long long pack_fu(float v, unsigned tag) {
    return (unsigned long long)__float_as_uint(v) | ((unsigned long long)tag << 32);
}
__device__ __forceinline__ unsigned long long ldsv(uint32_t a) {
    unsigned long long v; asm volatile("ld.volatile.shared.b64 %0,[%1];" : "=l"(v) : "r"(a)); return v;
}
__device__ __forceinline__ void stsv(uint32_t a, unsigned long long v) {
    asm volatile("st.volatile.shared.b64 [%0],%1;" :: "r"(a), "l"(v) : "memory");
}
__device__ __forceinline__ void stcl(uint32_t a, unsigned long long v) {
    asm volatile("st.shared::cluster.b64 [%0],%1;" :: "r"(a), "l"(v) : "memory");
}
__device__ __forceinline__ float poll_tag(uint32_t addr, unsigned want) {
    unsigned long long u = ldsv(addr);
    while ((unsigned)(u >> 32) != want) { __nanosleep(40); u = ldsv(addr); }
    return __uint_as_float((unsigned)u);
}

// ---------------------------------------------------------------------------
__global__ void coef_kernel(const float* __restrict__ x,
                            const float* __restrict__ eta_raw,
                            const float* __restrict__ alpha_raw) {
    float eta   = 0.2f / (1.0f + __expf(-eta_raw[0]));
    float alpha = 0.5f + 0.5f / (1.0f + __expf(-alpha_raw[0]));
    int warp  = (blockIdx.x * blockDim.x + threadIdx.x) >> 5;
    int lane  = threadIdx.x & 31;
    int nwarp = (gridDim.x * blockDim.x) >> 5;
    for (int row = warp; row < BB * SS; row += nwarp) {
        const float4* xr = reinterpret_cast<const float4*>(x + (size_t)row * DD);
        float4 a = xr[lane];
        float4 b = xr[lane + 32];
        float ss = a.x*a.x + a.y*a.y + a.z*a.z + a.w*a.w
                 + b.x*b.x + b.y*b.y + b.z*b.z + b.w*b.w;
        #pragma unroll
        for (int k = 16; k; k >>= 1) ss += __shfl_xor_sync(0xffffffffu, ss, k);
        if (lane == 0) {
            float n   = fmaxf(sqrtf(ss), 1e-6f);
            float inv = 1.0f / n;
            float c   = eta * (1.0f - inv) * inv;
            g_c[row]  = c;
            g_d[row]  = 2.0f * alpha * c + c * c * ss;
        }
    }
}

__global__ void g0_kernel(const float* __restrict__ M) {
    __shared__ float red[32];
    int tid = threadIdx.x;
    float s = 0.0f;
    for (int i = tid; i < DD * DD; i += 1024) {
        float v = M[i];
        s = fmaf(v, v, s);
    }
    #pragma unroll
    for (int k = 16; k; k >>= 1) s += __shfl_xor_sync(0xffffffffu, s, k);
    if ((tid & 31) == 0) red[tid >> 5] = s;
    __syncthreads();
    if (tid < 32) {
        float v = red[tid];
        #pragma unroll
        for (int k = 16; k; k >>= 1) v += __shfl_xor_sync(0xffffffffu, v, k);
        if (tid == 0) g_G0 = v;
    }
}

// ---------------------------------------------------------------------------
// Scan: 8-CTA cluster per batch. 16 row warps hold M (2 rows x 256 cols each,
// packed f32x2 in regs); 1 reducer warp runs the scalar ||M||^2 recurrence and
// the cross-CTA scalar exchange. No barriers in the loop; tagged rings with
// lag LAGR/LAGC make polls hit on first try in steady state.
// ---------------------------------------------------------------------------
__global__ void __cluster_dims__(CL, 1, 1) __launch_bounds__(NTHREADS, 1)
scan_kernel(const float* __restrict__ x,
            const float* __restrict__ Minit,
            const float* __restrict__ alpha_raw,
            float* __restrict__ out) {
    __shared__ unsigned long long wslot[RING][NROWW];   // {tag, warp ||w||^2 partial}
    __shared__ unsigned long long cslot[RING][CL];      // {tag, CTA partial} (DSMEM in)
    __shared__ unsigned long long resq[RING];           // {tag, Q_tau}
    __shared__ unsigned long long resf[RING];           // {tag, fold_tau}
    __shared__ unsigned long long wring[RING][NROWW];   // packed (w_row0, w_row1)
    __shared__ unsigned long long finslot;              // {SS+2, final pending scale}

    unsigned rank; asm("mov.u32 %0, %%cluster_ctarank;" : "=r"(rank));
    int batch = blockIdx.x / CL;
    int tid   = threadIdx.x;
    int wid   = tid >> 5;
    int lane  = tid & 31;

    for (int i = tid; i < RING * NROWW; i += NTHREADS) (&wslot[0][0])[i] = 0ull;
    for (int i = tid; i < RING * CL;    i += NTHREADS) (&cslot[0][0])[i] = 0ull;
    for (int i = tid; i < RING;         i += NTHREADS) { resq[i] = 0ull; resf[i] = 0ull; }
    if (tid == 0) finslot = 0ull;
    __syncthreads();
    asm volatile("barrier.cluster.arrive.aligned;" ::: "memory");
    asm volatile("barrier.cluster.wait.aligned;"   ::: "memory");

    float alpha = 0.5f + 0.5f / (1.0f + __expf(-alpha_raw[0]));
    const float* cb = g_c + batch * SS;
    uint32_t resq_b = (uint32_t)__cvta_generic_to_shared(resq);
    uint32_t resf_b = (uint32_t)__cvta_generic_to_shared(resf);

    if (wid < NROWW) {
        // ================= row warp: rows 2*wid, 2*wid+1 =================
        // column ownership per lane: [lane*4, lane*4+4) U [128+lane*4, 128+lane*4+4)
        int rg0 = (int)rank * 32 + wid * 2;
        const ulonglong2* xbp = (const ulonglong2*)(x + (size_t)batch * SS * DD);
        float* outb = out + (size_t)batch * SS * DD;

        unsigned long long m0[4], m1[4], xc[4];
        {
            const ulonglong2* mp = (const ulonglong2*)Minit + (size_t)rg0 * 64;
            ulonglong2 v0 = mp[lane], v1 = mp[32 + lane];
            m0[0] = v0.x; m0[1] = v0.y; m0[2] = v1.x; m0[3] = v1.y;
            v0 = mp[64 + lane]; v1 = mp[96 + lane];
            m1[0] = v0.x; m1[1] = v0.y; m1[2] = v1.x; m1[3] = v1.y;
        }
        {
            ulonglong2 v0 = xbp[lane], v1 = xbp[32 + lane];
            xc[0] = v0.x; xc[1] = v0.y; xc[2] = v1.x; xc[3] = v1.y;
        }
        float c_c = __ldg(cb);
        unsigned long long alpha2 = pk(alpha, alpha);
        uint32_t wsl_me = (uint32_t)__cvta_generic_to_shared(&wslot[0][wid]);
        uint32_t wrg_me = (uint32_t)__cvta_generic_to_shared(&wring[0][wid]);

        for (int t = 0; t < SS + LAGR; t++) {
            if (t < SS) {
                int slot = t & (RING - 1);
                int tn = (t + 1 < SS) ? t + 1 : t;
                const ulonglong2* xp = xbp + (size_t)tn * 64;
                ulonglong2 pv0 = xp[lane], pv1 = xp[32 + lane];
                float c_n = __ldg(cb + tn);

                // matvec (packed dot, 4 terms per row)
                unsigned long long a = mul2(m0[0], xc[0]);
                a = fma2(m0[1], xc[1], a); a = fma2(m0[2], xc[2], a); a = fma2(m0[3], xc[3], a);
                unsigned long long b = mul2(m1[0], xc[0]);
                b = fma2(m1[1], xc[1], b); b = fma2(m1[2], xc[2], b); b = fma2(m1[3], xc[3], b);
                float ax, ay, bx, by; unpk(a, ax, ay); unpk(b, bx, by);
                float wa = ax + ay, wb = bx + by;
                #pragma unroll
                for (int k = 16; k; k >>= 1) {
                    wa += __shfl_xor_sync(0xffffffffu, wa, k);
                    wb += __shfl_xor_sync(0xffffffffu, wb, k);
                }
                if (lane == 0) {
                    stsv(wsl_me + (uint32_t)slot * (NROWW * 8),
                         pack_fu(fmaf(wa, wa, wb * wb), (unsigned)(t + 1)));
                    stsv(wrg_me + (uint32_t)slot * (NROWW * 8), pk(wa, wb));
                }
                // rank-1 update (scale-free): m = alpha*m + (c*w)*x
                float ga = c_c * wa, gb = c_c * wb;
                unsigned long long g0 = pk(ga, ga), g1 = pk(gb, gb);
                #pragma unroll
                for (int j = 0; j < 4; j++) {
                    m0[j] = fma2(g0, xc[j], mul2(alpha2, m0[j]));
                    m1[j] = fma2(g1, xc[j], mul2(alpha2, m1[j]));
                }
                xc[0] = pv0.x; xc[1] = pv0.y; xc[2] = pv1.x; xc[3] = pv1.y;
                c_c = c_n;
            }
            if (t >= LAGR) {
                int tau = t - LAGR;
                int cs2 = tau & (RING - 1);
                float f = 0.0f;
                if (lane == 0) {
                    float Q = poll_tag(resq_b + (uint32_t)cs2 * 8, (unsigned)(tau + 1));
                    f       = poll_tag(resf_b + (uint32_t)cs2 * 8, (unsigned)(tau + 1));
                    unsigned long long wv = ldsv(wrg_me + (uint32_t)cs2 * (NROWW * 8));
                    float wx, wy; unpk(wv, wx, wy);
                    float2 o; o.x = Q * wx; o.y = Q * wy;
                    *reinterpret_cast<float2*>(outb + (size_t)tau * DD + rg0) = o;
                }
                f = __shfl_sync(0xffffffffu, f, 0);
                if (f != 1.0f) {   // rare, warp-uniform
                    unsigned long long f2 = pk(f, f);
                    #pragma unroll
                    for (int j = 0; j < 4; j++) { m0[j] = mul2(f2, m0[j]); m1[j] = mul2(f2, m1[j]); }
                }
            }
        }
        // final pending scale -> M_final
        float Pf = 0.0f;
        if (lane == 0)
            Pf = poll_tag((uint32_t)__cvta_generic_to_shared(&finslot), (unsigned)(SS + 2));
        Pf = __shfl_sync(0xffffffffu, Pf, 0);
        float* Mf = out + (size_t)BB * SS * DD + (size_t)batch * DD * DD;
        unsigned long long p2 = pk(Pf, Pf);
        ulonglong2* mo = (ulonglong2*)Mf + (size_t)rg0 * 64;
        ulonglong2 sv;
        sv.x = mul2(p2, m0[0]); sv.y = mul2(p2, m0[1]); mo[lane]       = sv;
        sv.x = mul2(p2, m0[2]); sv.y = mul2(p2, m0[3]); mo[32 + lane]  = sv;
        sv.x = mul2(p2, m1[0]); sv.y = mul2(p2, m1[1]); mo[64 + lane]  = sv;
        sv.x = mul2(p2, m1[2]); sv.y = mul2(p2, m1[3]); mo[96 + lane]  = sv;
    } else {
        // ================= reducer warp =================
        const float* db = g_d + batch * SS;
        float G = g_G0;
        float PendC = 1.0f, Fpend = 1.0f;
        // inverse-fold shift registers: fi8 = inv-fold decided 9 consumes ago
        float fi0 = 1.0f, fi1 = 1.0f, fi2 = 1.0f, fi3 = 1.0f, fi4 = 1.0f,
              fi5 = 1.0f, fi6 = 1.0f, fi7 = 1.0f, fi8 = 1.0f;
        float aa = alpha * alpha;
        uint32_t wsl_b = (uint32_t)__cvta_generic_to_shared(&wslot[0][0]);
        uint32_t csl_b = (uint32_t)__cvta_generic_to_shared(&cslot[0][0]);
        uint32_t rmt = 0;
        {
            uint32_t cb2 = (uint32_t)__cvta_generic_to_shared(&cslot[0][rank]);
            if (lane < CL)
                asm("mapa.shared::cluster.u32 %0,%1,%2;" : "=r"(rmt) : "r"(cb2), "r"(lane));
        }
        for (int t = 0; t < SS + LAGC; t++) {
            if (t < SS) {
                int slot = t & (RING - 1);
                float z = 0.0f;
                if (lane < NROWW)
                    z = poll_tag(wsl_b + (uint32_t)(slot * NROWW + lane) * 8, (unsigned)(t + 1));
                #pragma unroll
                for (int k = 16; k; k >>= 1) z += __shfl_xor_sync(0xffffffffu, z, k);
                if (lane < CL)
                    stcl(rmt + (uint32_t)slot * (CL * 8), pack_fu(z, (unsigned)(t + 1)));
            }
            if (t >= LAGC) {
                int tau = t - LAGC;
                int cs2 = tau & (RING - 1);
                float p = 0.0f;
                if (lane < CL)
                    p = poll_tag(csl_b + (uint32_t)(cs2 * CL + lane) * 8, (unsigned)(tau + 1));
                #pragma unroll
                for (int k = 16; k; k >>= 1) p += __shfl_xor_sync(0xffffffffu, p, k);
                // mature the fold decided LAGR+1 consumes ago
                Fpend *= fi8;
                fi8 = fi7; fi7 = fi6; fi6 = fi5; fi5 = fi4;
                fi4 = fi3; fi3 = fi2; fi2 = fi1; fi1 = fi0;
                float Q  = PendC * Fpend;          // C_tau / F_applied(tau)
                float y2 = Q * Q * p;              // true ||y_tau||^2
                float Gn = fmaf(aa, G, __ldg(db + tau) * y2);
                float s  = fminf(15.0f / (sqrtf(Gn) + 1e-6f), 1.0f);
                G = s * s * Gn;
                PendC *= s;
                float fnew = 1.0f, finew = 1.0f;
                if (PendC < 0.0625f) { fnew = PendC; finew = 1.0f / PendC; PendC = 1.0f; }
                Fpend *= fnew;
                fi0 = finew;
                if (lane == 0) {
                    stsv(resq_b + (uint32_t)cs2 * 8, pack_fu(Q,    (unsigned)(tau + 1)));
                    stsv(resf_b + (uint32_t)cs2 * 8, pack_fu(fnew, (unsigned)(tau + 1)));
                }
            }
        }
        if (lane == 0)
            stsv((uint32_t)__cvta_generic_to_shared(&finslot),
                 pack_fu(PendC, (unsigned)(SS + 2)));
    }
}

// ---------------------------------------------------------------------------
extern "C" void kernel_launch(void* const* d_in, const int* in_sizes, int n_in,
                              void* d_out, int out_size) {
    const float* x         = (const float*)d_in[0];
    const float* M_init    = (const float*)d_in[1];
    const float* eta_raw   = (const float*)d_in[2];
    const float* alpha_raw = (const float*)d_in[3];
    float*       out       = (float*)d_out;

    coef_kernel<<<1024, 256>>>(x, eta_raw, alpha_raw);
    g0_kernel<<<1, 1024>>>(M_init);
    scan_kernel<<<BB * CL, NTHREADS>>>(x, M_init, alpha_raw, out);
}